// round 3
// baseline (speedup 1.0000x reference)
#include <cuda_runtime.h>

// Blur_82471962018173: depthwise 4x4 FIR on (4,128,513,513) fp32 -> (4,128,512,512)
// out[y][x] = sum_{i,j} k[i][j] * in[y+i-1][x+j-1], zero-padded (pad=1 each side).
// Kernel k is rank-1 separable (outer product of [1,3,3,1]/... scaled); we factor
// it at runtime from the device kernel buffer: w_j = k[0][j], u_i = k[i][0]/k[0][0]
// (exact for this kernel since all entries are dyadic rationals in fp32).

#define W_IN  513
#define H_IN  513
#define W_OUT 512
#define H_OUT 512
#define ROWS_PER_THREAD 8
#define GROUPS 128            // 128 float4 column groups cover 512 output cols
#define TY 2                  // rows-threads per block
#define BLOCK_ROWS (ROWS_PER_THREAD * TY)   // 16 output rows per block

__global__ __launch_bounds__(GROUPS * TY, 2)
void blur_sep_kernel(const float* __restrict__ in,
                     const float* __restrict__ kern,
                     float* __restrict__ out)
{
    // gridDim.x = H_OUT / BLOCK_ROWS (=32), gridDim.y = N*C images
    const int img = blockIdx.y;
    const float* __restrict__ ip = in  + (size_t)img * (W_IN  * H_IN);
    float* __restrict__       op = out + (size_t)img * (W_OUT * H_OUT);

    const int g  = threadIdx.x;           // column group 0..127
    const int xc = g << 2;                // first output column of this thread
    const int y0 = blockIdx.x * BLOCK_ROWS + threadIdx.y * ROWS_PER_THREAD;

    // Separable factorization (uniform across threads -> uniform regs)
    const float w0 = __ldg(kern + 0);
    const float w1 = __ldg(kern + 1);
    const float w2 = __ldg(kern + 2);
    const float w3 = __ldg(kern + 3);
    const float inv = 1.0f / w0;
    const float u1 = __ldg(kern + 4)  * inv;
    const float u2 = __ldg(kern + 8)  * inv;
    const float u3 = __ldg(kern + 12) * inv;
    // u0 == 1 by construction

    // Column-edge predicates: only thread g==0 misses the left halo,
    // only g==GROUPS-1 misses the right halo (xc+5 == 513 is OOB).
    const bool lok = (xc > 0);
    const bool rok = (xc + 5 < W_IN);

    // Horizontally-filtered row (4 outputs) at input row r, zero outside [0, H_IN)
    auto hrow = [&](int r) -> float4 {
        float4 h = make_float4(0.f, 0.f, 0.f, 0.f);
        if (r < 0 || r >= H_IN) return h;
        const float* __restrict__ row = ip + (size_t)r * W_IN + xc;
        const float a0 = lok ? __ldg(row - 1) : 0.f;
        const float a1 = __ldg(row + 0);
        const float a2 = __ldg(row + 1);
        const float a3 = __ldg(row + 2);
        const float a4 = __ldg(row + 3);
        const float a5 = __ldg(row + 4);
        const float a6 = rok ? __ldg(row + 5) : 0.f;
        h.x = fmaf(w0, a0, fmaf(w1, a1, fmaf(w2, a2, w3 * a3)));
        h.y = fmaf(w0, a1, fmaf(w1, a2, fmaf(w2, a3, w3 * a4)));
        h.z = fmaf(w0, a2, fmaf(w1, a3, fmaf(w2, a4, w3 * a5)));
        h.w = fmaf(w0, a3, fmaf(w1, a4, fmaf(w2, a5, w3 * a6)));
        return h;
    };

    // Streaming vertical filter over 8 output rows: ring of 3 H-rows.
    float4 h0 = hrow(y0 - 1);
    float4 h1 = hrow(y0 + 0);
    float4 h2 = hrow(y0 + 1);

    #pragma unroll
    for (int r = 0; r < ROWS_PER_THREAD; ++r) {
        const float4 h3 = hrow(y0 + 2 + r);
        float4 o;
        o.x = fmaf(u1, h1.x, h0.x); o.x = fmaf(u2, h2.x, o.x); o.x = fmaf(u3, h3.x, o.x);
        o.y = fmaf(u1, h1.y, h0.y); o.y = fmaf(u2, h2.y, o.y); o.y = fmaf(u3, h3.y, o.y);
        o.z = fmaf(u1, h1.z, h0.z); o.z = fmaf(u2, h2.z, o.z); o.z = fmaf(u3, h3.z, o.z);
        o.w = fmaf(u1, h1.w, h0.w); o.w = fmaf(u2, h2.w, o.w); o.w = fmaf(u3, h3.w, o.w);
        *reinterpret_cast<float4*>(op + (size_t)(y0 + r) * W_OUT + xc) = o;
        h0 = h1; h1 = h2; h2 = h3;
    }
}

extern "C" void kernel_launch(void* const* d_in, const int* in_sizes, int n_in,
                              void* d_out, int out_size)
{
    const float* input  = (const float*)d_in[0];
    const float* kernel = (const float*)d_in[1];
    float*       output = (float*)d_out;

    const int n_images = in_sizes[0] / (W_IN * H_IN);   // N*C = 512

    dim3 block(GROUPS, TY, 1);                          // 256 threads
    dim3 grid(H_OUT / BLOCK_ROWS, n_images, 1);         // (32, 512)
    blur_sep_kernel<<<grid, block>>>(input, kernel, output);
}

// round 4
// speedup vs baseline: 1.0295x; 1.0295x over previous
#include <cuda_runtime.h>

// Blur_82471962018173: depthwise 4x4 FIR on (4,128,513,513) fp32 -> (4,128,512,512)
// out[y][x] = sum_{i,j} k[i][j] * in[y+i-1][x+j-1], zero-padded (pad=1 each side).
// Kernel is rank-1 separable: w_j = k[0][j], u_i = k[i][0]/k[0][0] (exact in fp32
// for this dyadic-rational kernel). Separable => 8 FMA per output instead of 16.
//
// R3: shared-memory staged version. R2 was L1-wavefront-bound (77% L1, 36% DRAM):
// scalar LDG with 16B lane stride burned ~5.6x the minimum L1 wavefronts.
// Here: (a) global loads are unit-stride cooperative stages (1 wavefront/LDG),
// (b) compute reads smem with skew idx = x + (x>>5), conflict-free for the
// stride-4-word lane pattern, (c) zero-pad rows are staged as zeros so the
// compute loop has no row predicates.

#define W_IN  513
#define H_IN  513
#define W_OUT 512
#define H_OUT 512
#define TILE_ROWS 16                 // output rows per block
#define IN_ROWS  (TILE_ROWS + 3)     // 19 staged input rows (1 top + 2 bottom halo)
#define SROW 529                     // skewed row stride: max sk(512) = 528
#define NTHREADS 256

__device__ __forceinline__ int sk(int x) { return x + (x >> 5); }

__global__ __launch_bounds__(NTHREADS, 4)
void blur_smem_kernel(const float* __restrict__ in,
                      const float* __restrict__ kern,
                      float* __restrict__ out)
{
    __shared__ float sm[IN_ROWS * SROW];   // ~40.2 KB

    const int img = blockIdx.y;
    const int y0  = blockIdx.x * TILE_ROWS;
    const float* __restrict__ ip = in  + (size_t)img * (W_IN  * H_IN);
    float* __restrict__       op = out + (size_t)img * (W_OUT * H_OUT);

    const int tid = threadIdx.x;

    // Separable factorization (uniform across threads), issued before staging
    // so the const loads overlap the stage.
    const float w0 = __ldg(kern + 0);
    const float w1 = __ldg(kern + 1);
    const float w2 = __ldg(kern + 2);
    const float w3 = __ldg(kern + 3);
    const float inv = 1.0f / w0;
    const float u1 = __ldg(kern + 4)  * inv;
    const float u2 = __ldg(kern + 8)  * inv;
    const float u3 = __ldg(kern + 12) * inv;   // u0 == 1

    // ---- Stage input rows y0-1 .. y0+17 into skewed smem (zeros outside image).
    // Unit-stride per warp: every LDG/STS warp instruction is fully coalesced
    // and STS banks are conflict-free (32-aligned x chunks).
    {
        const int gr0 = y0 - 1;
        #pragma unroll
        for (int lr = 0; lr < IN_ROWS; ++lr) {
            const int gr = gr0 + lr;
            float* __restrict__ srow = sm + lr * SROW;
            if (gr >= 0 && gr < H_IN) {
                const float* __restrict__ grow = ip + (size_t)gr * W_IN;
                #pragma unroll
                for (int x = tid; x < W_IN; x += NTHREADS)
                    srow[sk(x)] = __ldg(grow + x);
            } else {
                #pragma unroll
                for (int x = tid; x < W_IN; x += NTHREADS)
                    srow[sk(x)] = 0.f;
            }
        }
    }
    __syncthreads();

    // ---- Compute: thread = (column group g: 4 output cols) x (ty half: 8 rows)
    const int g  = tid & 127;
    const int ty = tid >> 7;
    const int xc = g << 2;
    const int yb = ty << 3;                 // local output row base (0 or 8)
    const bool lok = (g > 0);
    const bool rok = (g < 127);

    // Horizontally-filtered 4-wide chunk of staged row lr (lr in [0, IN_ROWS))
    auto hrow = [&](int lr) -> float4 {
        const float* __restrict__ s = sm + lr * SROW;
        const float a0 = lok ? s[sk(xc - 1)] : 0.f;
        const float a1 = s[sk(xc + 0)];
        const float a2 = s[sk(xc + 1)];
        const float a3 = s[sk(xc + 2)];
        const float a4 = s[sk(xc + 3)];
        const float a5 = s[sk(xc + 4)];
        const float a6 = rok ? s[sk(xc + 5)] : 0.f;
        float4 h;
        h.x = fmaf(w0, a0, fmaf(w1, a1, fmaf(w2, a2, w3 * a3)));
        h.y = fmaf(w0, a1, fmaf(w1, a2, fmaf(w2, a3, w3 * a4)));
        h.z = fmaf(w0, a2, fmaf(w1, a3, fmaf(w2, a4, w3 * a5)));
        h.w = fmaf(w0, a3, fmaf(w1, a4, fmaf(w2, a5, w3 * a6)));
        return h;
    };

    // Vertical streaming ring over 8 output rows.
    // out local row lo needs staged rows lo .. lo+3 (lr of global y-1 .. y+2).
    float4 h0 = hrow(yb + 0);
    float4 h1 = hrow(yb + 1);
    float4 h2 = hrow(yb + 2);

    #pragma unroll
    for (int r = 0; r < 8; ++r) {
        const float4 h3 = hrow(yb + 3 + r);
        float4 o;
        o.x = fmaf(u1, h1.x, h0.x); o.x = fmaf(u2, h2.x, o.x); o.x = fmaf(u3, h3.x, o.x);
        o.y = fmaf(u1, h1.y, h0.y); o.y = fmaf(u2, h2.y, o.y); o.y = fmaf(u3, h3.y, o.y);
        o.z = fmaf(u1, h1.z, h0.z); o.z = fmaf(u2, h2.z, o.z); o.z = fmaf(u3, h3.z, o.z);
        o.w = fmaf(u1, h1.w, h0.w); o.w = fmaf(u2, h2.w, o.w); o.w = fmaf(u3, h3.w, o.w);
        *reinterpret_cast<float4*>(op + (size_t)(y0 + yb + r) * W_OUT + xc) = o;
        h0 = h1; h1 = h2; h2 = h3;
    }
}

extern "C" void kernel_launch(void* const* d_in, const int* in_sizes, int n_in,
                              void* d_out, int out_size)
{
    const float* input  = (const float*)d_in[0];
    const float* kernel = (const float*)d_in[1];
    float*       output = (float*)d_out;

    const int n_images = in_sizes[0] / (W_IN * H_IN);   // N*C = 512

    dim3 block(NTHREADS, 1, 1);
    dim3 grid(H_OUT / TILE_ROWS, n_images, 1);          // (32, 512)
    blur_smem_kernel<<<grid, block>>>(input, kernel, output);
}

// round 9
// speedup vs baseline: 1.9395x; 1.8840x over previous
#include <cuda_runtime.h>
#include <cstdint>

// Blur_82471962018173: depthwise 4x4 FIR on (4,128,513,513) fp32 -> (4,128,512,512)
// Separable: w_j = k[0][j], u_i = k[i][0]/k[0][0] (exact: rank-1 dyadic kernel).
//
// R9: fixes R5/R8 device crash. Root cause: per-image base in+img*513^2 is only
// 4B-aligned (513^2 == 1 mod 4), so cp.async.cg.16 sources were misaligned for
// img % 4 != 0 -> illegal address -> container death. All alignment math is now
// in ABSOLUTE flat offsets from the tensor base (allocation-aligned).
// Design: cp.async 16B flat staging (unbounded MLP), column-per-thread compute
// (conflict-free smem, no skew), 512-thr CTAs / 39KB smem -> 4 CTAs/SM full occ.

#define W_IN  513
#define H_IN  513
#define W_OUT 512
#define H_OUT 512
#define TILE_ROWS 16
#define IN_ROWS   (TILE_ROWS + 3)          // 19 staged input rows
#define STAGE_FLOATS (IN_ROWS * W_IN)      // 9747
#define SMEM_FLOATS  (STAGE_FLOATS + 8)    // + shift(<=3) + pad
#define NT 512

__global__ __launch_bounds__(NT, 4)
void blur_pipe_kernel(const float* __restrict__ in,
                      const float* __restrict__ kern,
                      float* __restrict__ out)
{
    __shared__ __align__(16) float sm[SMEM_FLOATS];

    const int img = blockIdx.y;
    const int y0  = blockIdx.x * TILE_ROWS;
    const long gbase = (long)img * (W_IN * H_IN);
    float* __restrict__ op = out + (size_t)img * (W_OUT * H_OUT);
    const int tid = threadIdx.x;

    // Separable factorization (uniform across threads)
    const float w0 = __ldg(kern + 0);
    const float w1 = __ldg(kern + 1);
    const float w2 = __ldg(kern + 2);
    const float w3 = __ldg(kern + 3);
    const float inv = 1.0f / w0;
    const float u1 = __ldg(kern + 4)  * inv;
    const float u2 = __ldg(kern + 8)  * inv;
    const float u3 = __ldg(kern + 12) * inv;   // u0 == 1

    // ---- Flat staged region, ABSOLUTE offsets from tensor base `in`.
    // smem[i] holds absolute flat position aorg + i - shift, where
    // shift = aorg mod 4 makes global & shared 16B alignment coincide
    // (in[] is allocation-aligned; absolute index ≡ 0 mod 4 => 16B aligned).
    const int  r_lo = y0 - 1;
    const long aorg = gbase + (long)r_lo * W_IN;          // may be -513 (img 0)
    const int  shift = (int)(((aorg % 4) + 4) & 3);
    const int  v_lo = (r_lo < 0) ? 0 : r_lo;
    const int  v_hi = (y0 + IN_ROWS - 1 < H_IN) ? (y0 + IN_ROWS - 1) : H_IN;
    const long aflat_lo = gbase + (long)v_lo * W_IN;      // first valid abs idx
    const long aflat_hi = gbase + (long)v_hi * W_IN;      // one past last valid
    const int  s_lo = (int)(aflat_lo - aorg) + shift;
    const int  s_hi = (int)(aflat_hi - aorg) + shift;

    // Zero-fill smem head/tail (nonempty only for first/last row-tiles)
    for (int i = tid; i < s_lo; i += NT) sm[i] = 0.f;
    for (int i = s_hi + tid; i < STAGE_FLOATS + shift; i += NT) sm[i] = 0.f;

    // Bulk copy: 16B cp.async over the 4-aligned (absolute) interior,
    // scalar head/tail (at most 3 floats each).
    {
        const long af0 = (aflat_lo + 3) & ~3L;
        const long af1 = aflat_hi & ~3L;
        for (long f = aflat_lo + tid; f < af0; f += NT)
            sm[(int)(f - aorg) + shift] = __ldg(in + f);
        for (long f = af1 + tid; f < aflat_hi; f += NT)
            sm[(int)(f - aorg) + shift] = __ldg(in + f);

        const unsigned int n4 = (unsigned int)((af1 - af0) >> 2);  // ~2436 chunks
        const float4* __restrict__ gsrc = reinterpret_cast<const float4*>(in + af0);
        const unsigned int sbase =
            (unsigned int)__cvta_generic_to_shared(sm + ((int)(af0 - aorg) + shift));
        for (unsigned int i = (unsigned int)tid; i < n4; i += NT) {
            asm volatile("cp.async.cg.shared.global [%0], [%1], 16;\n"
                         :: "r"(sbase + i * 16u), "l"(gsrc + i));
        }
        asm volatile("cp.async.commit_group;\n" ::: "memory");
        asm volatile("cp.async.wait_group 0;\n" ::: "memory");
    }
    __syncthreads();

    // ---- Compute: one output column per thread, 16 rows streamed.
    // smem idx of (staged row lr, input col c) = shift + lr*W_IN + c.
    const int x   = tid;                  // output column 0..511
    const bool lok = (x > 0);             // input col x-1 valid?
    const bool rok = (x < W_OUT - 1);     // input col x+2 valid? (x+2 <= 512)
    const float* __restrict__ sb = sm + shift + x;

    auto hrow = [&](int lr) -> float {
        const float* __restrict__ row = sb + lr * W_IN;
        const float a0 = lok ? row[-1] : 0.f;
        const float a1 = row[0];
        const float a2 = row[1];
        const float a3 = rok ? row[2] : 0.f;
        return fmaf(w0, a0, fmaf(w1, a1, fmaf(w2, a2, w3 * a3)));
    };

    float h0 = hrow(0);
    float h1 = hrow(1);
    float h2 = hrow(2);

    float* __restrict__ orow = op + (size_t)y0 * W_OUT + x;
    #pragma unroll
    for (int r = 0; r < TILE_ROWS; ++r) {
        const float h3 = hrow(r + 3);
        float o = fmaf(u1, h1, h0);
        o = fmaf(u2, h2, o);
        o = fmaf(u3, h3, o);
        orow[(size_t)r * W_OUT] = o;
        h0 = h1; h1 = h2; h2 = h3;
    }
}

extern "C" void kernel_launch(void* const* d_in, const int* in_sizes, int n_in,
                              void* d_out, int out_size)
{
    (void)n_in; (void)out_size;
    const float* input  = (const float*)d_in[0];
    const float* kernel = (const float*)d_in[1];
    float*       output = (float*)d_out;

    const int n_images = in_sizes[0] / (W_IN * H_IN);   // N*C = 512

    dim3 block(NT, 1, 1);
    dim3 grid(H_OUT / TILE_ROWS, n_images, 1);          // (32, 512)
    blur_pipe_kernel<<<grid, block>>>(input, kernel, output);
}